// round 1
// baseline (speedup 1.0000x reference)
#include <cuda_runtime.h>
#include <cstdint>

// out[i, 0:32] = weight[b[i], 0:32]  (fp32), with out[0, :] = 0.
// N = 1,000,000 cells, Y_DIM = 32, N_BATCHES = 64.
// One thread per float4 => 8 threads per row. Warp = 4 rows = 512 B
// contiguous output, fully coalesced. weight table (8 KB) stays in L1.

static constexpr int Y_DIM = 32;
static constexpr int VEC_PER_ROW = Y_DIM / 4;  // 8 float4 per row

__global__ __launch_bounds__(256) void gather_rows_kernel(
    const int* __restrict__ b,          // [N] batch index per cell
    const float* __restrict__ weight,   // [N_BATCHES, 32]
    float4* __restrict__ out,           // [N, 8] as float4
    int n_vec)                          // N * 8
{
    int t = blockIdx.x * blockDim.x + threadIdx.x;
    if (t >= n_vec) return;

    int row  = t >> 3;        // cell index
    int col4 = t & 7;         // which float4 of the row

    int bi = __ldg(&b[row]);
    float4 v = __ldg(reinterpret_cast<const float4*>(weight) + bi * VEC_PER_ROW + col4);
    if (row == 0) v = make_float4(0.f, 0.f, 0.f, 0.f);
    out[t] = v;
}

extern "C" void kernel_launch(void* const* d_in, const int* in_sizes, int n_in,
                              void* d_out, int out_size) {
    // Inputs (metadata order): b [N,1] int32, weight [64,32] float32.
    const int*   b      = (const int*)d_in[0];
    const float* weight = (const float*)d_in[1];
    float4*      out    = (float4*)d_out;

    int n = in_sizes[0];            // N (b has N elements)
    int n_vec = n * VEC_PER_ROW;    // total float4 stores

    int threads = 256;
    int blocks = (n_vec + threads - 1) / threads;
    gather_rows_kernel<<<blocks, threads>>>(b, weight, out, n_vec);
}

// round 2
// speedup vs baseline: 1.4374x; 1.4374x over previous
#include <cuda_runtime.h>
#include <cstdint>

// out[i, 0:32] = weight[b[i], 0:32]  (fp32), out[0, :] = 0.
// N = 1,000,000 rows, Y_DIM = 32 -> 8 float4 per row, 8M float4 total.
//
// Each thread handles VPT=4 float4s at stride blockDim within a
// 1024-vec4 block tile: every store instruction is a fully-coalesced
// 512B warp transaction, and each thread carries 4 independent
// load->load->store chains (MLP=4) instead of 1.

static constexpr int Y_DIM = 32;
static constexpr int VEC_PER_ROW = Y_DIM / 4;   // 8
static constexpr int TPB = 256;
static constexpr int VPT = 4;                    // float4 per thread
static constexpr int TILE = TPB * VPT;           // 1024 vec4 per block

__global__ __launch_bounds__(TPB) void gather_rows_ilp4(
    const int* __restrict__ b,          // [N]
    const float* __restrict__ weight,   // [64, 32]
    float4* __restrict__ out,           // [N*8] float4
    int n_vec)
{
    const float4* __restrict__ w4 = reinterpret_cast<const float4*>(weight);

    int base = blockIdx.x * TILE + threadIdx.x;

    int  v[VPT];
    int  bi[VPT];
    bool ok[VPT];

    // Phase 1: gather indices (independent LDGs, L1-broadcast across 8 lanes)
    #pragma unroll
    for (int k = 0; k < VPT; k++) {
        v[k]  = base + k * TPB;
        ok[k] = v[k] < n_vec;
        int row = v[k] >> 3;
        bi[k] = ok[k] ? __ldg(&b[row]) : 0;
    }

    // Phase 2: gather weight vec4s (all hit L1, 8KB table)
    float4 val[VPT];
    #pragma unroll
    for (int k = 0; k < VPT; k++) {
        val[k] = __ldg(&w4[bi[k] * VEC_PER_ROW + (v[k] & 7)]);
        if ((v[k] >> 3) == 0) val[k] = make_float4(0.f, 0.f, 0.f, 0.f);
    }

    // Phase 3: streaming stores (write-once data; evict-first in L2)
    #pragma unroll
    for (int k = 0; k < VPT; k++) {
        if (ok[k]) __stcs(&out[v[k]], val[k]);
    }
}

extern "C" void kernel_launch(void* const* d_in, const int* in_sizes, int n_in,
                              void* d_out, int out_size) {
    const int*   b      = (const int*)d_in[0];
    const float* weight = (const float*)d_in[1];
    float4*      out    = (float4*)d_out;

    int n     = in_sizes[0];          // N rows
    int n_vec = n * VEC_PER_ROW;      // 8M float4

    int blocks = (n_vec + TILE - 1) / TILE;
    gather_rows_ilp4<<<blocks, TPB>>>(b, weight, out, n_vec);
}